// round 1
// baseline (speedup 1.0000x reference)
#include <cuda_runtime.h>
#include <math.h>

#define Bdim 64
#define Tdim 512
#define Idim 256
#define Hdim 512
#define BH   (Bdim*Hdim)   // 32768

// Scratch (device globals: no allocations allowed)
__device__ float g_xw[(size_t)Tdim*Bdim*Hdim];  // 64 MB, [T,B,H]
__device__ float g_h [(size_t)Tdim*Bdim*Hdim];  // 64 MB, [T,B,H]
__device__ int   g_bar[Tdim*8];                 // per-(step, batch-block) barrier counters

__global__ void zero_bar_k() {
    int i = blockIdx.x * blockDim.x + threadIdx.x;
    if (i < Tdim * 8) g_bar[i] = 0;
}

// ---------------------------------------------------------------------------
// Projection GEMM: g_xw[(t,b)][n] = sum_k Arow(m)[k] * W[n][k] + b1[n] + b2[n]
// M = 32768 rows (m = t*64 + b), N = 512, K = KD. BM=128, BN=64, BK=16.
// FIRST: A = x with layout [B,T,I]  -> row offset ((m&63)*T + (m>>6))*KD
// else : A = g_h with layout [T,B,H] -> row offset m*KD
// ---------------------------------------------------------------------------
template<int KD, bool FIRST>
__global__ __launch_bounds__(256) void proj_gemm(
    const float* __restrict__ xin, const float* __restrict__ W,
    const float* __restrict__ b1,  const float* __restrict__ b2)
{
    const float* __restrict__ A = FIRST ? xin : g_h;
    __shared__ __align__(16) float As[2][16 * 128];
    __shared__ __align__(16) float Bs[2][16 * 64];

    const int tid = threadIdx.x;
    const int m0 = blockIdx.y * 128;
    const int n0 = blockIdx.x * 64;
    const int tm = tid >> 4;     // 0..15  -> rows tm*8..tm*8+7
    const int tn = tid & 15;     // 0..15  -> cols tn*4..tn*4+3

    float acc[8][4];
    #pragma unroll
    for (int i = 0; i < 8; i++)
        #pragma unroll
        for (int j = 0; j < 4; j++) acc[i][j] = 0.f;

    int arow[2], akq[2];
    #pragma unroll
    for (int q = 0; q < 2; q++) {
        int idx = tid + q * 256;
        arow[q] = idx >> 2;
        akq[q]  = idx & 3;
    }
    const int bn = tid >> 2, bkq = tid & 3;

    size_t aoff[2];
    #pragma unroll
    for (int q = 0; q < 2; q++) {
        int m = m0 + arow[q];
        aoff[q] = FIRST ? ((size_t)(m & 63) * Tdim + (m >> 6)) * KD
                        : (size_t)m * KD;
    }
    const size_t boff = (size_t)(n0 + bn) * KD;

    float4 pa[2], pb;
    #pragma unroll
    for (int q = 0; q < 2; q++)
        pa[q] = *reinterpret_cast<const float4*>(A + aoff[q] + akq[q] * 4);
    pb = *reinterpret_cast<const float4*>(W + boff + bkq * 4);

    // store tile 0
    #pragma unroll
    for (int q = 0; q < 2; q++) {
        As[0][(akq[q]*4+0)*128 + arow[q]] = pa[q].x;
        As[0][(akq[q]*4+1)*128 + arow[q]] = pa[q].y;
        As[0][(akq[q]*4+2)*128 + arow[q]] = pa[q].z;
        As[0][(akq[q]*4+3)*128 + arow[q]] = pa[q].w;
    }
    Bs[0][(bkq*4+0)*64 + bn] = pb.x;
    Bs[0][(bkq*4+1)*64 + bn] = pb.y;
    Bs[0][(bkq*4+2)*64 + bn] = pb.z;
    Bs[0][(bkq*4+3)*64 + bn] = pb.w;
    __syncthreads();

    const int KT = KD / 16;
    int p = 0;
    for (int kt = 0; kt < KT; ++kt) {
        if (kt + 1 < KT) {
            int k0 = (kt + 1) * 16;
            #pragma unroll
            for (int q = 0; q < 2; q++)
                pa[q] = *reinterpret_cast<const float4*>(A + aoff[q] + k0 + akq[q]*4);
            pb = *reinterpret_cast<const float4*>(W + boff + k0 + bkq*4);
        }
        #pragma unroll
        for (int k = 0; k < 16; k++) {
            float af[8], bf[4];
            *reinterpret_cast<float4*>(&af[0]) =
                *reinterpret_cast<const float4*>(&As[p][k*128 + tm*8]);
            *reinterpret_cast<float4*>(&af[4]) =
                *reinterpret_cast<const float4*>(&As[p][k*128 + tm*8 + 4]);
            *reinterpret_cast<float4*>(&bf[0]) =
                *reinterpret_cast<const float4*>(&Bs[p][k*64 + tn*4]);
            #pragma unroll
            for (int i = 0; i < 8; i++)
                #pragma unroll
                for (int j = 0; j < 4; j++)
                    acc[i][j] = fmaf(af[i], bf[j], acc[i][j]);
        }
        if (kt + 1 < KT) {
            int np = p ^ 1;
            #pragma unroll
            for (int q = 0; q < 2; q++) {
                As[np][(akq[q]*4+0)*128 + arow[q]] = pa[q].x;
                As[np][(akq[q]*4+1)*128 + arow[q]] = pa[q].y;
                As[np][(akq[q]*4+2)*128 + arow[q]] = pa[q].z;
                As[np][(akq[q]*4+3)*128 + arow[q]] = pa[q].w;
            }
            Bs[np][(bkq*4+0)*64 + bn] = pb.x;
            Bs[np][(bkq*4+1)*64 + bn] = pb.y;
            Bs[np][(bkq*4+2)*64 + bn] = pb.z;
            Bs[np][(bkq*4+3)*64 + bn] = pb.w;
            __syncthreads();
            p = np;
        }
    }

    float bias[4];
    #pragma unroll
    for (int j = 0; j < 4; j++)
        bias[j] = b1[n0 + tn*4 + j] + b2[n0 + tn*4 + j];
    #pragma unroll
    for (int i = 0; i < 8; i++) {
        int m = m0 + tm*8 + i;
        float4 o;
        o.x = acc[i][0] + bias[0];
        o.y = acc[i][1] + bias[1];
        o.z = acc[i][2] + bias[2];
        o.w = acc[i][3] + bias[3];
        *reinterpret_cast<float4*>(&g_xw[(size_t)m * Hdim + n0 + tn*4]) = o;
    }
}

// ---------------------------------------------------------------------------
// Recurrent scan: h[t] = relu(xw[t] + h[t-1] @ Whh^T), persistent kernel.
// Grid (16 j-blocks, 8 b-blocks) = 128 CTAs, 256 threads each.
// Each warp w owns k-chunk [w*64, w*64+64); lane l owns column j = jblk*32+l.
// W slice lives in registers (16 float4 per thread) for all 512 steps.
// Cross-CTA sync: per-(step, b-block) counters; only 16 CTAs per barrier.
// ---------------------------------------------------------------------------
__global__ __launch_bounds__(256) void rnn_scan(const float* __restrict__ Whh)
{
    __shared__ __align__(16) float hs[8 * 512];        // h_prev slice (8 batch rows)
    __shared__ __align__(16) float part[8 * 8 * 32];   // per-warp partials

    const int tid  = threadIdx.x;
    const int w    = tid >> 5;
    const int lane = tid & 31;
    const int jblk = blockIdx.x;   // 0..15
    const int bblk = blockIdx.y;   // 0..7
    const int j = jblk * 32 + lane;
    const int rowbase = bblk * 8;

    // Weight-stationary registers: Whh[j][w*64 .. w*64+63]
    float4 wv[16];
    const float4* Wr = reinterpret_cast<const float4*>(Whh + (size_t)j * Hdim + w * 64);
    #pragma unroll
    for (int i = 0; i < 16; i++) wv[i] = Wr[i];

    float4* hs4 = reinterpret_cast<float4*>(hs);

    for (int t = 0; t < Tdim; ++t) {
        if (t > 0) {
            if (tid == 0) {
                while (atomicAdd(&g_bar[(t - 1) * 8 + bblk], 0) < 16) { }
                __threadfence();
            }
            __syncthreads();
            const float4* src = reinterpret_cast<const float4*>(
                g_h + (size_t)(t - 1) * BH + (size_t)rowbase * Hdim);
            #pragma unroll
            for (int r = 0; r < 4; r++)
                hs4[tid + r * 256] = __ldcg(&src[tid + r * 256]);
        } else {
            float4 z = make_float4(0.f, 0.f, 0.f, 0.f);
            #pragma unroll
            for (int r = 0; r < 4; r++) hs4[tid + r * 256] = z;
        }
        __syncthreads();

        float acc[8];
        #pragma unroll
        for (int b = 0; b < 8; b++) acc[b] = 0.f;
        #pragma unroll
        for (int i = 0; i < 16; i++) {
            float4 w4 = wv[i];
            #pragma unroll
            for (int b = 0; b < 8; b++) {
                float4 h4 = hs4[b * 128 + w * 16 + i];   // warp-uniform -> broadcast
                acc[b] = fmaf(h4.w, w4.w,
                          fmaf(h4.z, w4.z,
                           fmaf(h4.y, w4.y,
                            fmaf(h4.x, w4.x, acc[b]))));
            }
        }
        #pragma unroll
        for (int b = 0; b < 8; b++)
            part[(w * 8 + b) * 32 + lane] = acc[b];
        __syncthreads();

        {
            int b2 = tid >> 5, j2 = tid & 31;
            float s = 0.f;
            #pragma unroll
            for (int ww = 0; ww < 8; ww++)
                s += part[(ww * 8 + b2) * 32 + j2];
            size_t off = (size_t)t * BH + (size_t)(rowbase + b2) * Hdim + jblk * 32 + j2;
            float v = g_xw[off] + s;
            g_h[off] = fmaxf(v, 0.f);
        }
        __syncthreads();
        if (tid == 0) {
            __threadfence();
            atomicAdd(&g_bar[t * 8 + bblk], 1);
        }
    }
}

// ---------------------------------------------------------------------------
// FC + sigmoid: out[b*T + t] = sigmoid(dot(h1[t][b], W_fc) + b_fc)
// One warp per (t,b) row.
// ---------------------------------------------------------------------------
__global__ __launch_bounds__(256) void fc_sigmoid(
    const float* __restrict__ wfc, const float* __restrict__ bfc,
    float* __restrict__ out)
{
    int gw   = (blockIdx.x * blockDim.x + threadIdx.x) >> 5;  // 0..32767
    int lane = threadIdx.x & 31;
    int t = gw >> 6, b = gw & 63;

    const float4* hp = reinterpret_cast<const float4*>(g_h + (size_t)gw * Hdim);
    const float4* wp = reinterpret_cast<const float4*>(wfc);
    float s = 0.f;
    #pragma unroll
    for (int r = 0; r < 4; r++) {
        float4 hv = hp[lane + r * 32];
        float4 wv = wp[lane + r * 32];
        s += hv.x * wv.x + hv.y * wv.y + hv.z * wv.z + hv.w * wv.w;
    }
    #pragma unroll
    for (int o = 16; o > 0; o >>= 1)
        s += __shfl_xor_sync(0xffffffffu, s, o);
    if (lane == 0) {
        float v = s + bfc[0];
        out[(size_t)b * Tdim + t] = 1.f / (1.f + expf(-v));
    }
}

// ---------------------------------------------------------------------------
extern "C" void kernel_launch(void* const* d_in, const int* in_sizes, int n_in,
                              void* d_out, int out_size)
{
    (void)in_sizes; (void)n_in; (void)out_size;
    const float* x    = (const float*)d_in[0];
    const float* Wih0 = (const float*)d_in[1];
    const float* Whh0 = (const float*)d_in[2];
    const float* bih0 = (const float*)d_in[3];
    const float* bhh0 = (const float*)d_in[4];
    const float* Wih1 = (const float*)d_in[5];
    const float* Whh1 = (const float*)d_in[6];
    const float* bih1 = (const float*)d_in[7];
    const float* bhh1 = (const float*)d_in[8];
    const float* Wfc  = (const float*)d_in[9];
    const float* bfc  = (const float*)d_in[10];
    float* out = (float*)d_out;

    dim3 gemm_grid(8, 256);   // N/64, M/128
    dim3 scan_grid(16, 8);    // j-blocks, b-blocks

    // Layer 0
    zero_bar_k<<<16, 256>>>();
    proj_gemm<Idim, true><<<gemm_grid, 256>>>(x, Wih0, bih0, bhh0);
    rnn_scan<<<scan_grid, 256>>>(Whh0);

    // Layer 1
    zero_bar_k<<<16, 256>>>();
    proj_gemm<Hdim, false><<<gemm_grid, 256>>>(x, Wih1, bih1, bhh1);
    rnn_scan<<<scan_grid, 256>>>(Whh1);

    // Head
    fc_sigmoid<<<4096, 256>>>(Wfc, bfc, out);
}